// round 10
// baseline (speedup 1.0000x reference)
#include <cuda_runtime.h>
#include <cstdint>

constexpr int RGRID  = 740;    // reduce: 148 SMs * 5 blocks, exactly one wave @48 regs
constexpr int SGRID  = 1184;   // scale: empirically fastest (R4) for the store stream
constexpr int BLOCK  = 256;
constexpr int UNROLL = 8;

// Per-block partial sums of squares. Fully overwritten every replay.
__device__ float g_partials[RGRID];

struct TensorSet {
    const float4* p[5];
    float4*       o[5];   // output slice base (concatenated layout), vec4 units
    long          n[5];   // vec4 element counts
};

__device__ __forceinline__ float dot4_acc(float4 v, float a) {
    a = fmaf(v.x, v.x, a);
    a = fmaf(v.y, v.y, a);
    a = fmaf(v.z, v.z, a);
    a = fmaf(v.w, v.w, a);
    return a;
}

// ---------------- Pass 1: grid-stride sum of squares (R6 config: 121.6us) ----
__global__ void __launch_bounds__(BLOCK, 5) reduce_sumsq_kernel(TensorSet ts) {
    const long stride = (long)RGRID * BLOCK;
    const long base   = (long)blockIdx.x * BLOCK + threadIdx.x;

    float a[UNROLL];
    #pragma unroll
    for (int k = 0; k < UNROLL; ++k) a[k] = 0.f;

    #pragma unroll
    for (int t = 0; t < 5; ++t) {
        const float4* __restrict__ p = ts.p[t];
        const long n = ts.n[t];
        long i = base;
        for (; i + (UNROLL - 1) * stride < n; i += UNROLL * stride) {
            float4 v[UNROLL];
            #pragma unroll
            for (int k = 0; k < UNROLL; ++k) v[k] = __ldcs(p + i + k * stride);
            #pragma unroll
            for (int k = 0; k < UNROLL; ++k) a[k] = dot4_acc(v[k], a[k]);
        }
        for (; i < n; i += stride)
            a[0] = dot4_acc(__ldcs(p + i), a[0]);
    }

    float acc = 0.f;
    #pragma unroll
    for (int k = 0; k < UNROLL; ++k) acc += a[k];

    #pragma unroll
    for (int off = 16; off > 0; off >>= 1)
        acc += __shfl_xor_sync(0xFFFFFFFFu, acc, off);

    __shared__ float warp_sums[BLOCK / 32];
    const int lane = threadIdx.x & 31;
    const int wid  = threadIdx.x >> 5;
    if (lane == 0) warp_sums[wid] = acc;
    __syncthreads();

    if (wid == 0) {
        float s = (lane < (BLOCK >> 5)) ? warp_sums[lane] : 0.0f;
        #pragma unroll
        for (int off = 4; off > 0; off >>= 1)
            s += __shfl_xor_sync(0xFFFFFFFFu, s, off);
        if (lane == 0) {
            g_partials[blockIdx.x] = s;
            __threadfence();
        }
    }
    __syncthreads();
    // PDL: this block is done -> allow dependent (scale) blocks to launch into
    // the freed SM slots while the rest of the grid drains.
    cudaTriggerProgrammaticLaunchCompletion();
}

// ---------------- Pass 2: contiguous-chunk scale (R4 config: 252.6us) --------
__global__ void __launch_bounds__(BLOCK) scale_kernel(TensorSet ts) {
    // Prologue (no dependency on pass 1): chunk math can run during overlap.
    const int lane = threadIdx.x & 31;
    const int wid  = threadIdx.x >> 5;

    // Wait until pass 1's memory is visible, then reduce partials.
    cudaGridDependencySynchronize();

    double d = 0.0;
    for (int i = threadIdx.x; i < RGRID; i += BLOCK)
        d += (double)g_partials[i];

    #pragma unroll
    for (int off = 16; off > 0; off >>= 1)
        d += __shfl_xor_sync(0xFFFFFFFFu, d, off);

    __shared__ double warp_sums_d[BLOCK / 32];
    __shared__ float  s_scale;
    if (lane == 0) warp_sums_d[wid] = d;
    __syncthreads();
    if (wid == 0) {
        double s = (lane < (BLOCK >> 5)) ? warp_sums_d[lane] : 0.0;
        #pragma unroll
        for (int off = 4; off > 0; off >>= 1)
            s += __shfl_xor_sync(0xFFFFFFFFu, s, off);
        if (lane == 0) {
            float norm = sqrtf((float)s);
            s_scale = (norm > 1.0f) ? (1.0f / (norm + 1e-6f)) : 1.0f;
        }
    }
    __syncthreads();
    const float scale = s_scale;

    // Streaming scale, contiguous per-block chunks (R4 pattern).
    #pragma unroll
    for (int t = 0; t < 5; ++t) {
        const float4* __restrict__ p = ts.p[t];
        float4* __restrict__ o = ts.o[t];
        const long n = ts.n[t];
        const long chunk = (n + SGRID - 1) / SGRID;
        const long start = (long)blockIdx.x * chunk;
        const long end   = (start + chunk < n) ? (start + chunk) : n;

        long i = start + threadIdx.x;
        for (; i + (UNROLL - 1) * BLOCK < end; i += UNROLL * BLOCK) {
            float4 v[UNROLL];
            #pragma unroll
            for (int k = 0; k < UNROLL; ++k) v[k] = __ldcs(p + i + k * BLOCK);
            #pragma unroll
            for (int k = 0; k < UNROLL; ++k) {
                v[k].x *= scale; v[k].y *= scale;
                v[k].z *= scale; v[k].w *= scale;
            }
            #pragma unroll
            for (int k = 0; k < UNROLL; ++k) __stcs(o + i + k * BLOCK, v[k]);
        }
        for (; i < end; i += BLOCK) {
            float4 v = __ldcs(p + i);
            v.x *= scale; v.y *= scale; v.z *= scale; v.w *= scale;
            __stcs(o + i, v);
        }
    }
}

extern "C" void kernel_launch(void* const* d_in, const int* in_sizes, int n_in,
                              void* d_out, int out_size) {
    TensorSet ts;
    long off = 0;
    float* out = (float*)d_out;
    for (int t = 0; t < 5; ++t) {
        ts.p[t] = (const float4*)d_in[t];
        ts.o[t] = (float4*)(out + off);
        ts.n[t] = (long)in_sizes[t] / 4;   // all counts divisible by 4
        off += (long)in_sizes[t];
    }

    reduce_sumsq_kernel<<<RGRID, BLOCK>>>(ts);

    // Scale kernel with Programmatic Dependent Launch: may begin launching
    // while reduce drains; device-side cudaGridDependencySynchronize() provides
    // the ordering + memory visibility for g_partials.
    cudaLaunchConfig_t cfg = {};
    cfg.gridDim  = dim3(SGRID, 1, 1);
    cfg.blockDim = dim3(BLOCK, 1, 1);
    cfg.dynamicSmemBytes = 0;
    cfg.stream = 0;
    cudaLaunchAttribute attr[1];
    attr[0].id = cudaLaunchAttributeProgrammaticStreamSerialization;
    attr[0].val.programmaticStreamSerializationAllowed = 1;
    cfg.attrs = attr;
    cfg.numAttrs = 1;
    cudaError_t e = cudaLaunchKernelEx(&cfg, scale_kernel, ts);
    if (e != cudaSuccess) {
        // Fallback: plain serialized launch (still correct).
        scale_kernel<<<SGRID, BLOCK>>>(ts);
    }
}

// round 11
// speedup vs baseline: 1.0058x; 1.0058x over previous
#include <cuda_runtime.h>
#include <cstdint>

constexpr int RGRID  = 740;    // reduce: 148 SMs * 5 blocks, one wave @48 regs (R6 best: 121.6us)
constexpr int SGRID  = 1184;   // scale: contiguous chunks, empirically fastest (R10: 251.0us)
constexpr int BLOCK  = 256;
constexpr int UNROLL = 8;

// Per-block partial sums of squares. Fully overwritten every replay.
__device__ float g_partials[RGRID];

struct TensorSet {
    const float4* p[5];
    float4*       o[5];   // output slice base (concatenated layout), vec4 units
    long          n[5];   // vec4 element counts
};

__device__ __forceinline__ float dot4_acc(float4 v, float a) {
    a = fmaf(v.x, v.x, a);
    a = fmaf(v.y, v.y, a);
    a = fmaf(v.z, v.z, a);
    a = fmaf(v.w, v.w, a);
    return a;
}

// ---------------- Pass 1: grid-stride sum of squares (R6 config) ------------
__global__ void __launch_bounds__(BLOCK, 5) reduce_sumsq_kernel(TensorSet ts) {
    const long stride = (long)RGRID * BLOCK;
    const long base   = (long)blockIdx.x * BLOCK + threadIdx.x;

    float a[UNROLL];
    #pragma unroll
    for (int k = 0; k < UNROLL; ++k) a[k] = 0.f;

    #pragma unroll
    for (int t = 0; t < 5; ++t) {
        const float4* __restrict__ p = ts.p[t];
        const long n = ts.n[t];
        long i = base;
        for (; i + (UNROLL - 1) * stride < n; i += UNROLL * stride) {
            float4 v[UNROLL];
            #pragma unroll
            for (int k = 0; k < UNROLL; ++k) v[k] = __ldcs(p + i + k * stride);
            #pragma unroll
            for (int k = 0; k < UNROLL; ++k) a[k] = dot4_acc(v[k], a[k]);
        }
        for (; i < n; i += stride)
            a[0] = dot4_acc(__ldcs(p + i), a[0]);
    }

    float acc = 0.f;
    #pragma unroll
    for (int k = 0; k < UNROLL; ++k) acc += a[k];

    #pragma unroll
    for (int off = 16; off > 0; off >>= 1)
        acc += __shfl_xor_sync(0xFFFFFFFFu, acc, off);

    __shared__ float warp_sums[BLOCK / 32];
    const int lane = threadIdx.x & 31;
    const int wid  = threadIdx.x >> 5;
    if (lane == 0) warp_sums[wid] = acc;
    __syncthreads();

    if (wid == 0) {
        float s = (lane < (BLOCK >> 5)) ? warp_sums[lane] : 0.0f;
        #pragma unroll
        for (int off = 4; off > 0; off >>= 1)
            s += __shfl_xor_sync(0xFFFFFFFFu, s, off);
        if (lane == 0)
            g_partials[blockIdx.x] = s;
    }
}

// ---------------- Pass 2: contiguous-chunk scale (R10 config) ---------------
__global__ void __launch_bounds__(BLOCK) scale_kernel(TensorSet ts) {
    const int lane = threadIdx.x & 31;
    const int wid  = threadIdx.x >> 5;

    // Redundant per-block partial reduction: fixed order -> deterministic,
    // identical scale in every block; 3KB array is L2-broadcast, free.
    double d = 0.0;
    for (int i = threadIdx.x; i < RGRID; i += BLOCK)
        d += (double)g_partials[i];

    #pragma unroll
    for (int off = 16; off > 0; off >>= 1)
        d += __shfl_xor_sync(0xFFFFFFFFu, d, off);

    __shared__ double warp_sums_d[BLOCK / 32];
    __shared__ float  s_scale;
    if (lane == 0) warp_sums_d[wid] = d;
    __syncthreads();
    if (wid == 0) {
        double s = (lane < (BLOCK >> 5)) ? warp_sums_d[lane] : 0.0;
        #pragma unroll
        for (int off = 4; off > 0; off >>= 1)
            s += __shfl_xor_sync(0xFFFFFFFFu, s, off);
        if (lane == 0) {
            float norm = sqrtf((float)s);
            s_scale = (norm > 1.0f) ? (1.0f / (norm + 1e-6f)) : 1.0f;
        }
    }
    __syncthreads();
    const float scale = s_scale;

    // Streaming scale, contiguous per-block chunks.
    #pragma unroll
    for (int t = 0; t < 5; ++t) {
        const float4* __restrict__ p = ts.p[t];
        float4* __restrict__ o = ts.o[t];
        const long n = ts.n[t];
        const long chunk = (n + SGRID - 1) / SGRID;
        const long start = (long)blockIdx.x * chunk;
        const long end   = (start + chunk < n) ? (start + chunk) : n;

        long i = start + threadIdx.x;
        for (; i + (UNROLL - 1) * BLOCK < end; i += UNROLL * BLOCK) {
            float4 v[UNROLL];
            #pragma unroll
            for (int k = 0; k < UNROLL; ++k) v[k] = __ldcs(p + i + k * BLOCK);
            #pragma unroll
            for (int k = 0; k < UNROLL; ++k) {
                v[k].x *= scale; v[k].y *= scale;
                v[k].z *= scale; v[k].w *= scale;
            }
            #pragma unroll
            for (int k = 0; k < UNROLL; ++k) __stcs(o + i + k * BLOCK, v[k]);
        }
        for (; i < end; i += BLOCK) {
            float4 v = __ldcs(p + i);
            v.x *= scale; v.y *= scale; v.z *= scale; v.w *= scale;
            __stcs(o + i, v);
        }
    }
}

extern "C" void kernel_launch(void* const* d_in, const int* in_sizes, int n_in,
                              void* d_out, int out_size) {
    TensorSet ts;
    long off = 0;
    float* out = (float*)d_out;
    for (int t = 0; t < 5; ++t) {
        ts.p[t] = (const float4*)d_in[t];
        ts.o[t] = (float4*)(out + off);
        ts.n[t] = (long)in_sizes[t] / 4;   // all counts divisible by 4
        off += (long)in_sizes[t];
    }

    reduce_sumsq_kernel<<<RGRID, BLOCK>>>(ts);
    scale_kernel<<<SGRID, BLOCK>>>(ts);
}

// round 12
// speedup vs baseline: 1.0096x; 1.0039x over previous
#include <cuda_runtime.h>
#include <cstdint>

constexpr int GRID   = 740;    // 148 SMs * 5 blocks -> one wave (<=50 regs, 33KB smem)
constexpr int BLOCK  = 256;
constexpr int UNROLL = 8;
constexpr int PF     = 4;      // float4 prefetched across the barrier per thread
constexpr int STASH_V4   = BLOCK * UNROLL;            // 2048 float4 = 32 KB per block
constexpr long STASH_TOT = (long)GRID * STASH_V4;     // 23.7 MB slice of t4

__device__ float g_partials[GRID];
// Monotonic ticket barrier; never reset (each launch consumes GRID tickets).
__device__ unsigned long long g_bar;

struct TensorSet {
    const float4* p[5];
    float4*       o[5];
    long          n[5];
};

__device__ __forceinline__ float dot4_acc(float4 v, float a) {
    a = fmaf(v.x, v.x, a);
    a = fmaf(v.y, v.y, a);
    a = fmaf(v.z, v.z, a);
    a = fmaf(v.w, v.w, a);
    return a;
}

__device__ __forceinline__ void sweep_reduce(const float4* __restrict__ p,
                                             long n, long base, long stride,
                                             float a[UNROLL]) {
    long i = base;
    for (; i + (UNROLL - 1) * stride < n; i += UNROLL * stride) {
        float4 v[UNROLL];
        #pragma unroll
        for (int k = 0; k < UNROLL; ++k) v[k] = __ldcs(p + i + k * stride);
        #pragma unroll
        for (int k = 0; k < UNROLL; ++k) a[k] = dot4_acc(v[k], a[k]);
    }
    for (; i < n; i += stride)
        a[0] = dot4_acc(__ldcs(p + i), a[0]);
}

__device__ __forceinline__ void sweep_scale(const float4* __restrict__ p,
                                            float4* __restrict__ o,
                                            long lo, long hi, float scale) {
    long i = lo + threadIdx.x;
    for (; i + (UNROLL - 1) * BLOCK < hi; i += UNROLL * BLOCK) {
        float4 v[UNROLL];
        #pragma unroll
        for (int k = 0; k < UNROLL; ++k) v[k] = __ldcs(p + i + k * BLOCK);
        #pragma unroll
        for (int k = 0; k < UNROLL; ++k) {
            v[k].x *= scale; v[k].y *= scale;
            v[k].z *= scale; v[k].w *= scale;
        }
        #pragma unroll
        for (int k = 0; k < UNROLL; ++k) __stcs(o + i + k * BLOCK, v[k]);
    }
    for (; i < hi; i += BLOCK) {
        float4 v = __ldcs(p + i);
        v.x *= scale; v.y *= scale; v.z *= scale; v.w *= scale;
        __stcs(o + i, v);
    }
}

__device__ __forceinline__ void chunk_range(long n, long& lo, long& hi) {
    long chunk = ((n + GRID - 1) / GRID + 7) & ~7L;   // 128B-aligned chunks
    lo = (long)blockIdx.x * chunk;
    hi = lo + chunk;
    if (lo > n) lo = n;
    if (hi > n) hi = n;
}

__global__ void __launch_bounds__(BLOCK, 5) fused_clip_kernel(TensorSet ts) {
    __shared__ float4 stash[STASH_V4];                 // 32 KB
    __shared__ float  warp_sums[BLOCK / 32];
    __shared__ double warp_sums_d[BLOCK / 32];
    __shared__ float  s_scale;

    const long stride = (long)GRID * BLOCK;
    const long base   = (long)blockIdx.x * BLOCK + threadIdx.x;
    const int  lane   = threadIdx.x & 31;
    const int  wid    = threadIdx.x >> 5;

    const long n4       = ts.n[4];
    const long stash_lo = n4 - STASH_TOT;              // > 0 for these shapes
    const long body4    = stash_lo;

    // ---------------- Phase 1: sum of squares ----------------
    float a[UNROLL];
    #pragma unroll
    for (int k = 0; k < UNROLL; ++k) a[k] = 0.f;

    #pragma unroll
    for (int t = 0; t < 4; ++t)
        sweep_reduce(ts.p[t], ts.n[t], base, stride, a);
    sweep_reduce(ts.p[4], body4, base, stride, a);

    // Stash slice of t4 tail into SMEM (single read, reused for the store pass).
    {
        const long rb = stash_lo + (long)blockIdx.x * STASH_V4;
        const float4* __restrict__ p4 = ts.p[4];
        #pragma unroll
        for (int k = 0; k < UNROLL; ++k) {
            float4 v = __ldcs(p4 + rb + threadIdx.x + k * BLOCK);
            stash[threadIdx.x + k * BLOCK] = v;
            a[k] = dot4_acc(v, a[k]);
        }
    }

    float acc = 0.f;
    #pragma unroll
    for (int k = 0; k < UNROLL; ++k) acc += a[k];
    #pragma unroll
    for (int off = 16; off > 0; off >>= 1)
        acc += __shfl_xor_sync(0xFFFFFFFFu, acc, off);
    if (lane == 0) warp_sums[wid] = acc;
    __syncthreads();

    unsigned long long bar_target = 0;
    if (wid == 0) {
        float s = (lane < (BLOCK >> 5)) ? warp_sums[lane] : 0.0f;
        #pragma unroll
        for (int off = 4; off > 0; off >>= 1)
            s += __shfl_xor_sync(0xFFFFFFFFu, s, off);
        if (lane == 0) {
            __stcg(&g_partials[blockIdx.x], s);
            __threadfence();                            // release partial
            unsigned long long t = atomicAdd(&g_bar, 1ULL);
            bar_target = (t / GRID) * GRID + GRID;      // arrive EARLY
        }
    }

    // ---- Prefetch phase-2 head chunk of t0 into registers (independent of
    // the barrier): these loads fill the drain window with useful LTS work.
    long t0_lo, t0_hi; chunk_range(ts.n[0], t0_lo, t0_hi);
    const bool pf_ok = (t0_lo + PF * BLOCK <= t0_hi);
    float4 pf[PF];
    if (pf_ok) {
        const float4* __restrict__ p0 = ts.p[0];
        #pragma unroll
        for (int k = 0; k < PF; ++k)
            pf[k] = __ldcs(p0 + t0_lo + threadIdx.x + k * BLOCK);
    }

    // ---- Wait for all blocks (thread 0 polls; loads above already in flight).
    if (wid == 0 && lane == 0) {
        volatile unsigned long long* bar = &g_bar;
        while (*bar < bar_target) __nanosleep(128);
        __threadfence();                                // acquire partials
    }
    __syncthreads();

    // ---------------- Scale factor (redundant per block, deterministic) -----
    double d = 0.0;
    for (int i = threadIdx.x; i < GRID; i += BLOCK)
        d += (double)__ldcg(&g_partials[i]);
    #pragma unroll
    for (int off = 16; off > 0; off >>= 1)
        d += __shfl_xor_sync(0xFFFFFFFFu, d, off);
    if (lane == 0) warp_sums_d[wid] = d;
    __syncthreads();
    if (wid == 0) {
        double s = (lane < (BLOCK >> 5)) ? warp_sums_d[lane] : 0.0;
        #pragma unroll
        for (int off = 4; off > 0; off >>= 1)
            s += __shfl_xor_sync(0xFFFFFFFFu, s, off);
        if (lane == 0) {
            float norm = sqrtf((float)s);
            s_scale = (norm > 1.0f) ? (1.0f / (norm + 1e-6f)) : 1.0f;
        }
    }
    __syncthreads();
    const float scale = s_scale;

    // ---------------- Phase 2: scale + store ----------------
    // 1) Prefetched t0 head: data already in registers.
    if (pf_ok) {
        float4* __restrict__ o0 = ts.o[0];
        #pragma unroll
        for (int k = 0; k < PF; ++k) {
            float4 v = pf[k];
            v.x *= scale; v.y *= scale; v.z *= scale; v.w *= scale;
            __stcs(o0 + t0_lo + threadIdx.x + k * BLOCK, v);
        }
    }
    // 2) Stash: pure writes, zero LTS reads.
    {
        const long rb = stash_lo + (long)blockIdx.x * STASH_V4;
        float4* __restrict__ o4 = ts.o[4];
        #pragma unroll
        for (int k = 0; k < UNROLL; ++k) {
            float4 v = stash[threadIdx.x + k * BLOCK];
            v.x *= scale; v.y *= scale; v.z *= scale; v.w *= scale;
            __stcs(o4 + rb + threadIdx.x + k * BLOCK, v);
        }
    }
    // 3) Rest of t0 chunk, then t1..t3, then t4 body. Contiguous chunks.
    sweep_scale(ts.p[0], ts.o[0], pf_ok ? t0_lo + PF * BLOCK : t0_lo, t0_hi, scale);
    #pragma unroll
    for (int t = 1; t < 4; ++t) {
        long lo, hi; chunk_range(ts.n[t], lo, hi);
        sweep_scale(ts.p[t], ts.o[t], lo, hi, scale);
    }
    {
        long lo, hi; chunk_range(body4, lo, hi);
        sweep_scale(ts.p[4], ts.o[4], lo, hi, scale);
    }
}

extern "C" void kernel_launch(void* const* d_in, const int* in_sizes, int n_in,
                              void* d_out, int out_size) {
    TensorSet ts;
    long off = 0;
    float* out = (float*)d_out;
    for (int t = 0; t < 5; ++t) {
        ts.p[t] = (const float4*)d_in[t];
        ts.o[t] = (float4*)(out + off);
        ts.n[t] = (long)in_sizes[t] / 4;   // all counts divisible by 4
        off += (long)in_sizes[t];
    }

    fused_clip_kernel<<<GRID, BLOCK>>>(ts);
}

// round 15
// speedup vs baseline: 1.0503x; 1.0403x over previous
#include <cuda_runtime.h>
#include <cstdint>

constexpr int GRID   = 740;    // 148 SMs * 5 blocks -> one wave
constexpr int BLOCK  = 256;
constexpr int UNROLL = 8;
constexpr long CH1   = (long)BLOCK * UNROLL;   // 2048 vec4 = 32 KB reduce chunk
constexpr long CH2   = (long)BLOCK * 4;        // 1024 vec4 = 16 KB scale chunk
constexpr int STASH_V4 = BLOCK * UNROLL;       // 2048 float4 = 32 KB per block

// Per-chunk partials (phase 1). Values are deterministic per chunk index.
__device__ float g_part1[32768];
__device__ float g_part_stash[GRID];
// Work-stealing counters: self-reset by the provably-last puller each launch.
__device__ unsigned long long g_w1, g_w2;
// Monotonic barrier counters (never reset; round derived from ticket).
__device__ unsigned long long g_arrive, g_ready;
__device__ float g_scale;

struct Params {
    const float4* p[5];
    float4*       o[5];
    long dn[5];      // dynamic-space sizes (t4 entry excludes the stash tail)
    long cb1[6];     // cumulative chunk bases, phase 1
    long cb2[6];     // cumulative chunk bases, phase 2
    long nch1, nch2;
    long stash_lo;   // start of stash region within t4 (vec4 units)
};

__device__ __forceinline__ float dot4_acc(float4 v, float a) {
    a = fmaf(v.x, v.x, a);
    a = fmaf(v.y, v.y, a);
    a = fmaf(v.z, v.z, a);
    a = fmaf(v.w, v.w, a);
    return a;
}

// Fixed-order block reduction of one float per thread -> thread (0,0) result.
__device__ __forceinline__ float block_reduce(float acc, float* wsum,
                                              int lane, int wid) {
    #pragma unroll
    for (int off = 16; off > 0; off >>= 1)
        acc += __shfl_xor_sync(0xFFFFFFFFu, acc, off);
    if (lane == 0) wsum[wid] = acc;
    __syncthreads();
    float s = 0.f;
    if (wid == 0) {
        s = (lane < (BLOCK >> 5)) ? wsum[lane] : 0.0f;
        #pragma unroll
        for (int off = 4; off > 0; off >>= 1)
            s += __shfl_xor_sync(0xFFFFFFFFu, s, off);
    }
    return s;
}

__global__ void __launch_bounds__(BLOCK, 5) fused_clip_kernel(Params P) {
    __shared__ float4 stash[STASH_V4];           // 32 KB
    __shared__ float  wsum[BLOCK / 32];
    __shared__ double wsumd[BLOCK / 32];
    __shared__ float  s_scale;
    __shared__ long   s_tk;
    __shared__ int    s_last;
    __shared__ unsigned long long s_round;

    const int tid  = threadIdx.x;
    const int lane = tid & 31;
    const int wid  = tid >> 5;

    // ================= Phase 1a: static stash slice of t4 tail =============
    {
        const long rb = P.stash_lo + (long)blockIdx.x * STASH_V4;
        const float4* __restrict__ p4 = P.p[4];
        float a[UNROLL];
        #pragma unroll
        for (int k = 0; k < UNROLL; ++k) {
            float4 v = __ldcs(p4 + rb + tid + k * BLOCK);
            stash[tid + k * BLOCK] = v;
            a[k] = dot4_acc(v, 0.f);
        }
        float acc = ((a[0] + a[1]) + (a[2] + a[3])) +
                    ((a[4] + a[5]) + (a[6] + a[7]));
        float s = block_reduce(acc, wsum, lane, wid);
        if (wid == 0 && lane == 0) __stcg(&g_part_stash[blockIdx.x], s);
        __syncthreads();                          // wsum reusable
    }

    // ================= Phase 1b: dynamic chunk reduce =======================
    if (tid == 0) s_tk = (long)atomicAdd(&g_w1, 1ULL);
    __syncthreads();
    long t = s_tk;
    while (t < P.nch1) {
        unsigned long long nxt;
        if (tid == 0) nxt = atomicAdd(&g_w1, 1ULL);   // prefetch next ticket

        int tt = 0;
        while (t >= P.cb1[tt + 1]) ++tt;
        const long lo = (t - P.cb1[tt]) * CH1;
        const long nt = P.dn[tt];
        const float4* __restrict__ p = P.p[tt];

        float a[UNROLL];
        #pragma unroll
        for (int k = 0; k < UNROLL; ++k) a[k] = 0.f;

        if (lo + CH1 <= nt) {                          // full chunk, no guards
            float4 v[UNROLL];
            #pragma unroll
            for (int k = 0; k < UNROLL; ++k) v[k] = __ldcs(p + lo + tid + k * BLOCK);
            #pragma unroll
            for (int k = 0; k < UNROLL; ++k) a[k] = dot4_acc(v[k], a[k]);
        } else {                                       // tail chunk, guarded
            #pragma unroll
            for (int k = 0; k < UNROLL; ++k) {
                long i = lo + tid + k * BLOCK;
                if (i < nt) a[k] = dot4_acc(__ldcs(p + i), a[k]);
            }
        }
        float acc = ((a[0] + a[1]) + (a[2] + a[3])) +
                    ((a[4] + a[5]) + (a[6] + a[7]));
        float s = block_reduce(acc, wsum, lane, wid);
        if (wid == 0 && lane == 0) __stcg(&g_part1[t], s);
        __syncthreads();                               // wsum consumed
        if (tid == 0) s_tk = (long)nxt;
        __syncthreads();
        t = s_tk;
    }
    // Provably-last puller (all NCH1+GRID pulls done) resets for next replay.
    if (tid == 0 && t == P.nch1 + GRID - 1) atomicExch(&g_w1, 0ULL);

    // ================= Barrier + scale computation ==========================
    __threadfence();                                   // release partials
    if (tid == 0) {
        unsigned long long at = atomicAdd(&g_arrive, 1ULL);
        s_last  = ((at % GRID) == (unsigned long long)(GRID - 1));
        s_round = at / GRID + 1;
    }
    __syncthreads();

    if (s_last) {
        __threadfence();                               // acquire all partials
        // Fixed-order deterministic total: 4 interleaved double accumulators.
        double d0 = 0.0, d1 = 0.0, d2 = 0.0, d3 = 0.0;
        for (long i = tid; i < P.nch1; i += 4L * BLOCK) {
            d0 += (double)__ldcg(&g_part1[i]);
            if (i + BLOCK     < P.nch1) d1 += (double)__ldcg(&g_part1[i + BLOCK]);
            if (i + 2 * BLOCK < P.nch1) d2 += (double)__ldcg(&g_part1[i + 2 * BLOCK]);
            if (i + 3 * BLOCK < P.nch1) d3 += (double)__ldcg(&g_part1[i + 3 * BLOCK]);
        }
        double d = ((d0 + d1) + (d2 + d3));
        for (int i = tid; i < GRID; i += BLOCK)
            d += (double)__ldcg(&g_part_stash[i]);

        #pragma unroll
        for (int off = 16; off > 0; off >>= 1)
            d += __shfl_xor_sync(0xFFFFFFFFu, d, off);
        if (lane == 0) wsumd[wid] = d;
        __syncthreads();
        if (wid == 0) {
            double s = (lane < (BLOCK >> 5)) ? wsumd[lane] : 0.0;
            #pragma unroll
            for (int off = 4; off > 0; off >>= 1)
                s += __shfl_xor_sync(0xFFFFFFFFu, s, off);
            if (lane == 0) {
                float norm  = sqrtf((float)s);
                float scale = (norm > 1.0f) ? (1.0f / (norm + 1e-6f)) : 1.0f;
                __stcg(&g_scale, scale);
                __threadfence();                       // publish scale
                atomicAdd(&g_ready, 1ULL);
                s_scale = scale;
            }
        }
    } else {
        if (tid == 0) {
            volatile unsigned long long* r = &g_ready;
            while (*r < s_round) __nanosleep(64);
            __threadfence();                           // acquire scale
            s_scale = __ldcg(&g_scale);
        }
    }
    __syncthreads();
    const float scale = s_scale;

    // ================= Phase 2a: stash store (zero LTS reads) ==============
    {
        const long rb = P.stash_lo + (long)blockIdx.x * STASH_V4;
        float4* __restrict__ o4 = P.o[4];
        #pragma unroll
        for (int k = 0; k < UNROLL; ++k) {
            float4 v = stash[tid + k * BLOCK];
            v.x *= scale; v.y *= scale; v.z *= scale; v.w *= scale;
            __stcs(o4 + rb + tid + k * BLOCK, v);
        }
    }

    // ================= Phase 2b: dynamic chunk scale+store ==================
    if (tid == 0) s_tk = (long)atomicAdd(&g_w2, 1ULL);
    __syncthreads();
    t = s_tk;
    while (t < P.nch2) {
        unsigned long long nxt;
        if (tid == 0) nxt = atomicAdd(&g_w2, 1ULL);

        int tt = 0;
        while (t >= P.cb2[tt + 1]) ++tt;
        const long lo = (t - P.cb2[tt]) * CH2;
        const long nt = P.dn[tt];
        const float4* __restrict__ p = P.p[tt];
        float4* __restrict__ o = P.o[tt];

        if (lo + CH2 <= nt) {
            float4 v[4];
            #pragma unroll
            for (int k = 0; k < 4; ++k) v[k] = __ldcs(p + lo + tid + k * BLOCK);
            #pragma unroll
            for (int k = 0; k < 4; ++k) {
                v[k].x *= scale; v[k].y *= scale;
                v[k].z *= scale; v[k].w *= scale;
            }
            #pragma unroll
            for (int k = 0; k < 4; ++k) __stcs(o + lo + tid + k * BLOCK, v[k]);
        } else {
            #pragma unroll
            for (int k = 0; k < 4; ++k) {
                long i = lo + tid + k * BLOCK;
                if (i < nt) {
                    float4 v = __ldcs(p + i);
                    v.x *= scale; v.y *= scale; v.z *= scale; v.w *= scale;
                    __stcs(o + i, v);
                }
            }
        }
        __syncthreads();
        if (tid == 0) s_tk = (long)nxt;
        __syncthreads();
        t = s_tk;
    }
    if (tid == 0 && t == P.nch2 + GRID - 1) atomicExch(&g_w2, 0ULL);
}

extern "C" void kernel_launch(void* const* d_in, const int* in_sizes, int n_in,
                              void* d_out, int out_size) {
    Params P;
    long off = 0;
    float* out = (float*)d_out;
    long n[5];
    for (int t = 0; t < 5; ++t) {
        P.p[t] = (const float4*)d_in[t];
        P.o[t] = (float4*)(out + off);
        n[t]   = (long)in_sizes[t] / 4;    // all counts divisible by 4
        off += (long)in_sizes[t];
    }
    P.stash_lo = n[4] - (long)GRID * STASH_V4;   // > 0 for these shapes
    for (int t = 0; t < 4; ++t) P.dn[t] = n[t];
    P.dn[4] = P.stash_lo;                        // t4 dynamic space excludes stash

    P.cb1[0] = 0; P.cb2[0] = 0;
    for (int t = 0; t < 5; ++t) {
        P.cb1[t + 1] = P.cb1[t] + (P.dn[t] + CH1 - 1) / CH1;
        P.cb2[t + 1] = P.cb2[t] + (P.dn[t] + CH2 - 1) / CH2;
    }
    P.nch1 = P.cb1[5];
    P.nch2 = P.cb2[5];
    // g_part1 capacity guard (23975 expected; array holds 32768).

    fused_clip_kernel<<<GRID, BLOCK>>>(P);
}